// round 5
// baseline (speedup 1.0000x reference)
#include <cuda_runtime.h>
#include <cuda_bf16.h>
#include <math.h>

#define H 512
#define W 512
#define BATCH 16
#define NPIX (H*W)
#define CA 0.955f
#define CB 1.3693f
#define CINF 1e6f
#define BIG 1e30f

#define DT_T 128
#define CPT 4

#define LBLK 256
#define BPI 16
#define NLB (BATCH*BPI)

// dynamic smem layout: mbits[512*18] then seedb[512*16]
#define MB_WORDS (H*18)
#define SB_WORDS (H*16)
#define DT_SMEM ((MB_WORDS + SB_WORDS) * 4)

// ---------------- device scratch ----------------
__device__ float g_dist[BATCH*NPIX];
__device__ float g_mx[BATCH];
__device__ int   g_flags[BATCH];
__device__ float g_part[NLB*5];

__global__ __launch_bounds__(DT_T) void dt_kernel(const int* __restrict__ target) {
    extern __shared__ unsigned dynsmem[];
    unsigned* mbits = dynsmem;              // [H][18] guard-padded mask bitmap
    unsigned* seedb = dynsmem + MB_WORDS;   // [H][16] seed bitmap

    const int img = blockIdx.x;
    const int* tg = target + img * NPIX;
    float* dd = g_dist + img * NPIX;

    const int tid  = threadIdx.x;
    const int lane = tid & 31;
    const int wrp  = tid >> 5;
    const int sl   = tid & 7;
    const int sg   = tid >> 3;            // 0..15
    const int col0 = tid * CPT;
    const unsigned FM = 0xffffffffu;

    __shared__ __align__(16) float sg_agg[2][16];
    __shared__ float sA[2][4];            // lane31 slot per warp
    __shared__ float sB[2][4];            // lane0 slot per warp
    __shared__ float wred[4];
    __shared__ int sflag[2];

    if (tid < 2) sflag[tid] = 0;
    for (int r = tid; r < H; r += DT_T) {
        mbits[r * 18 + 0]  = 0u;
        mbits[r * 18 + 17] = 0u;
    }
    __syncthreads();

    // ---- build mask bitmap + flags ----
    bool any1 = false, any0 = false;
    for (int r = 0; r < H; r++) {
        int4 tv = *(const int4*)(tg + r * W + col0);
        unsigned nib = (unsigned)(tv.x != 0) | ((unsigned)(tv.y != 0) << 1)
                     | ((unsigned)(tv.z != 0) << 2) | ((unsigned)(tv.w != 0) << 3);
        any1 |= (nib != 0u);
        any0 |= (nib != 15u);
        unsigned word = nib << (4 * sl);
        word |= __shfl_xor_sync(FM, word, 1);
        word |= __shfl_xor_sync(FM, word, 2);
        word |= __shfl_xor_sync(FM, word, 4);
        if (sl == 0) mbits[r * 18 + 1 + sg] = word;
    }
    if (__any_sync(FM, any1) && lane == 0) atomicOr(&sflag[0], 1);
    if (__any_sync(FM, any0) && lane == 0) atomicOr(&sflag[1], 1);
    __syncthreads();
    const int hasb = sflag[0] & sflag[1];

    // ---- precompute seed bitmap (word-parallel dilate/erode) ----
    for (int idx = tid; idx < H * 16; idx += DT_T) {
        int r = idx >> 4, w = idx & 15;
        unsigned sw;
        if (hasb) {
            unsigned dil = 0u, ero = 0xffffffffu;
            #pragma unroll
            for (int dr = -1; dr <= 1; dr++) {
                int r2 = r + dr;
                if (r2 < 0 || r2 >= H) continue;   // OR: row OOB=0; AND: row OOB=1
                unsigned M  = mbits[r2 * 18 + 1 + w];
                unsigned Ml = mbits[r2 * 18 + w];        // zero guard (OR)
                unsigned Mr = mbits[r2 * 18 + 2 + w];
                unsigned Mlg = (w == 0)  ? 0xffffffffu : Ml;   // AND: col OOB=1
                unsigned Mrg = (w == 15) ? 0xffffffffu : Mr;
                dil |= M | __funnelshift_l(Ml, M, 1) | __funnelshift_r(M, Mr, 1);
                ero &= M & __funnelshift_l(Mlg, M, 1) & __funnelshift_r(M, Mrg, 1);
            }
            sw = dil & ~ero;
        } else {
            sw = ~mbits[r * 18 + 1 + w];
        }
        seedb[r * 16 + w] = sw;
    }
    __syncthreads();

    const float aj0 = CA * (float)(col0);
    const float aj1 = CA * (float)(col0 + 1);
    const float aj2 = CA * (float)(col0 + 2);
    const float aj3 = CA * (float)(col0 + 3);
    const float ajL3 = CA * (float)(col0 - 1);
    const float ajR0 = CA * (float)(col0 + 4);

    // ================= forward pass =================
    float p0 = CINF, p1 = CINF, p2 = CINF, p3 = CINF, pvL = CINF, pvR = CINF;
    unsigned sw = seedb[(tid >> 3)];
    const int shamt = 4 * sl;

    for (int i = 0; i < H; i++) {
        unsigned nib = sw >> shamt;
        float d0 = (nib & 1u) ? 0.0f : CINF;
        float d1 = (nib & 2u) ? 0.0f : CINF;
        float d2 = (nib & 4u) ? 0.0f : CINF;
        float d3 = (nib & 8u) ? 0.0f : CINF;

        float m0 = fminf(fminf(d0, p0 + CA), fminf(pvL + CB, p1 + CB));
        float m1 = fminf(fminf(d1, p1 + CA), fminf(p0 + CB, p2 + CB));
        float m2 = fminf(fminf(d2, p2 + CA), fminf(p1 + CB, p3 + CB));
        float m3 = fminf(fminf(d3, p3 + CA), fminf(p2 + CB, pvR + CB));

        float v0 = m0 - aj0, v1 = m1 - aj1, v2 = m2 - aj2, v3 = m3 - aj3;
        float pm0 = v0;
        float pm1 = fminf(pm0, v1);
        float pm2 = fminf(pm1, v2);
        float pm3 = fminf(pm2, v3);

        float s = pm3, o;
        o = __shfl_up_sync(FM, s, 1); if (sl >= 1) s = fminf(s, o);
        o = __shfl_up_sync(FM, s, 2); if (sl >= 2) s = fminf(s, o);
        o = __shfl_up_sync(FM, s, 4); if (sl >= 4) s = fminf(s, o);
        float sLr = __shfl_up_sync(FM, s, 1);
        float excl = (sl == 0) ? BIG : sLr;
        float pmR0r = __shfl_down_sync(FM, v0, 1);

        const int pb = i & 1;
        if (sl == 7)    sg_agg[pb][sg] = s;
        if (lane == 31) sA[pb][wrp] = s;
        if (lane == 0)  sB[pb][wrp] = v0;
        if (i < H - 1)  sw = seedb[(i + 1) * 16 + (tid >> 3)];
        __syncthreads();

        float raw[16];
        {
            const float4* sq = (const float4*)sg_agg[pb];
            float4 q0 = sq[0], q1 = sq[1], q2 = sq[2], q3 = sq[3];
            raw[0]=q0.x; raw[1]=q0.y; raw[2]=q0.z; raw[3]=q0.w;
            raw[4]=q1.x; raw[5]=q1.y; raw[6]=q1.z; raw[7]=q1.w;
            raw[8]=q2.x; raw[9]=q2.y; raw[10]=q2.z; raw[11]=q2.w;
            raw[12]=q3.x; raw[13]=q3.y; raw[14]=q3.z; raw[15]=q3.w;
        }
        float a[16], b[16];
        #pragma unroll
        for (int k = 0; k < 16; k++) {
            a[k] = (k < sg)     ? raw[k] : BIG;   // tree k<sg
            b[k] = (k + 1 < sg) ? raw[k] : BIG;   // tree k<sg-1
        }
        #pragma unroll
        for (int st = 8; st > 0; st >>= 1)
            #pragma unroll
            for (int k = 0; k < 8; k++)
                if (k < st) { a[k] = fminf(a[k], a[k + st]); b[k] = fminf(b[k], b[k + st]); }
        float u0 = a[0], uv = b[0];

        float base = fminf(u0, excl);
        float c0 = aj0 + fminf(base, pm0);
        float c1 = aj1 + fminf(base, pm1);
        float c2 = aj2 + fminf(base, pm2);
        float c3 = aj3 + fminf(base, pm3);
        float4 outv = {c0, c1, c2, c3};
        *(float4*)(dd + i * W + col0) = outv;

        float sLv = (lane == 0) ? sA[pb][(wrp == 0) ? 0 : wrp - 1] : sLr;
        float treeL = (sl == 0) ? uv : u0;
        pvL = (tid == 0) ? CINF : (ajL3 + fminf(treeL, sLv));

        float pmR0v = (lane == 31) ? sB[pb][(wrp == 3) ? 3 : wrp + 1] : pmR0r;
        float treeR = (sl == 7) ? fminf(u0, s) : u0;
        float eR = (sl == 7) ? BIG : s;
        pvR = (tid == DT_T - 1) ? CINF : (ajR0 + fminf(treeR, fminf(eR, pmR0v)));

        p0 = c0; p1 = c1; p2 = c2; p3 = c3;
    }

    __syncthreads();

    // ================= backward pass =================
    const float ar0 = CA * (float)(W - 1 - col0);
    const float ar1 = CA * (float)(W - 2 - col0);
    const float ar2 = CA * (float)(W - 3 - col0);
    const float ar3 = CA * (float)(W - 4 - col0);
    const float arL3 = CA * (float)(W - col0);
    const float arR0 = CA * (float)(W - 5 - col0);

    p0 = CINF; p1 = CINF; p2 = CINF; p3 = CINF; pvL = CINF; pvR = CINF;
    float lmax = 0.0f;
    float4 nxt = *(const float4*)(dd + (H - 1) * W + col0);

    for (int i = H - 1; i >= 0; i--) {
        float4 dr = nxt;
        if (i > 0) nxt = *(const float4*)(dd + (i - 1) * W + col0);

        float m0 = fminf(fminf(dr.x, p0 + CA), fminf(pvL + CB, p1 + CB));
        float m1 = fminf(fminf(dr.y, p1 + CA), fminf(p0 + CB, p2 + CB));
        float m2 = fminf(fminf(dr.z, p2 + CA), fminf(p1 + CB, p3 + CB));
        float m3 = fminf(fminf(dr.w, p3 + CA), fminf(p2 + CB, pvR + CB));

        float v0 = m0 - ar0, v1 = m1 - ar1, v2 = m2 - ar2, v3 = m3 - ar3;
        float pm3 = v3;
        float pm2 = fminf(v2, pm3);
        float pm1 = fminf(v1, pm2);
        float pm0 = fminf(v0, pm1);

        float s = pm0, o;
        o = __shfl_down_sync(FM, s, 1); if (sl <= 6) s = fminf(s, o);
        o = __shfl_down_sync(FM, s, 2); if (sl <= 5) s = fminf(s, o);
        o = __shfl_down_sync(FM, s, 4); if (sl <= 3) s = fminf(s, o);
        float sRr = __shfl_down_sync(FM, s, 1);
        float excl = (sl == 7) ? BIG : sRr;
        float pmL3r = __shfl_up_sync(FM, v3, 1);

        const int pb = i & 1;
        if (sl == 0)    sg_agg[pb][sg] = s;
        if (lane == 31) sA[pb][wrp] = v3;
        if (lane == 0)  sB[pb][wrp] = s;
        __syncthreads();

        float raw[16];
        {
            const float4* sq = (const float4*)sg_agg[pb];
            float4 q0 = sq[0], q1 = sq[1], q2 = sq[2], q3 = sq[3];
            raw[0]=q0.x; raw[1]=q0.y; raw[2]=q0.z; raw[3]=q0.w;
            raw[4]=q1.x; raw[5]=q1.y; raw[6]=q1.z; raw[7]=q1.w;
            raw[8]=q2.x; raw[9]=q2.y; raw[10]=q2.z; raw[11]=q2.w;
            raw[12]=q3.x; raw[13]=q3.y; raw[14]=q3.z; raw[15]=q3.w;
        }
        float a[16], b[16];
        #pragma unroll
        for (int k = 0; k < 16; k++) {
            a[k] = (k > sg)     ? raw[k] : BIG;   // tree k>sg
            b[k] = (k > sg + 1) ? raw[k] : BIG;   // tree k>sg+1
        }
        #pragma unroll
        for (int st = 8; st > 0; st >>= 1)
            #pragma unroll
            for (int k = 0; k < 8; k++)
                if (k < st) { a[k] = fminf(a[k], a[k + st]); b[k] = fminf(b[k], b[k + st]); }
        float u0 = a[0], uv = b[0];

        float base = fminf(u0, excl);
        float c0 = ar0 + fminf(base, pm0);
        float c1 = ar1 + fminf(base, pm1);
        float c2 = ar2 + fminf(base, pm2);
        float c3 = ar3 + fminf(base, pm3);
        float4 outv = {c0, c1, c2, c3};
        *(float4*)(dd + i * W + col0) = outv;
        lmax = fmaxf(lmax, fmaxf(fmaxf(c0, c1), fmaxf(c2, c3)));

        float sRv = (lane == 31) ? sB[pb][(wrp == 3) ? 3 : wrp + 1] : sRr;
        float treeR = (sl == 7) ? uv : u0;
        pvR = (tid == DT_T - 1) ? CINF : (arR0 + fminf(treeR, sRv));

        float pmL3v = (lane == 0) ? sA[pb][(wrp == 0) ? 0 : wrp - 1] : pmL3r;
        float treeL = (sl == 0) ? fminf(u0, s) : u0;
        pvL = (tid == 0) ? CINF : (arL3 + fminf(treeL, fminf(s, pmL3v)));

        p0 = c0; p1 = c1; p2 = c2; p3 = c3;
    }

    // ---- per-image max + flags ----
    #pragma unroll
    for (int d = 16; d > 0; d >>= 1)
        lmax = fmaxf(lmax, __shfl_xor_sync(FM, lmax, d));
    if (lane == 0) wred[wrp] = lmax;
    __syncthreads();
    if (tid == 0) {
        float mm = 0.0f;
        for (int w = 0; w < 4; w++) mm = fmaxf(mm, wred[w]);
        g_mx[img] = mm;
        g_flags[img] = sflag[0] | (sflag[1] << 1);
    }
}

// ---------------- loss partial sums ----------------
__global__ __launch_bounds__(LBLK) void loss_partial(const float* __restrict__ pred,
                                                     const int* __restrict__ target) {
    const int img = blockIdx.x / BPI;
    const int sub = blockIdx.x % BPI;
    const int base = img * NPIX;
    const float mx = g_mx[img];
    const int hfg = g_flags[img] & 1;
    const float inv = 1.0f / fmaxf(mx, 1e-12f);
    const int usediv = (mx > 0.0f) ? 1 : 0;

    float sF = 0.f, sB = 0.f, sP = 0.f, sT = 0.f, sPT = 0.f;
    for (int idx = sub * LBLK + threadIdx.x; idx < NPIX; idx += BPI * LBLK) {
        float x = pred[base + idx];
        int tv = target[base + idx];
        float d = g_dist[base + idx];
        float p = 1.0f / (1.0f + expf(-x));
        float ax = fabsf(x);
        float bce = log1pf(expf(-ax)) + (tv ? fmaxf(-x, 0.0f) : fmaxf(x, 0.0f));
        float pt = tv ? p : (1.0f - p);
        float omp = 1.0f - pt;
        float alpha = tv ? 0.25f : 0.75f;
        sF += alpha * omp * omp * bce;
        float dn = hfg ? (usediv ? d * inv : d) : 1.0f;
        sB += omp * (1.0f + dn);
        sP += p;
        if (tv) { sT += 1.0f; sPT += p; }
    }

    float vals[5] = {sF, sB, sP, sT, sPT};
    #pragma unroll
    for (int k = 0; k < 5; k++) {
        float v = vals[k];
        #pragma unroll
        for (int d = 16; d > 0; d >>= 1) v += __shfl_xor_sync(0xffffffffu, v, d);
        vals[k] = v;
    }
    __shared__ float s5[LBLK / 32][5];
    int lane = threadIdx.x & 31, wid = threadIdx.x >> 5;
    if (lane == 0) {
        #pragma unroll
        for (int k = 0; k < 5; k++) s5[wid][k] = vals[k];
    }
    __syncthreads();
    if (threadIdx.x == 0) {
        #pragma unroll
        for (int k = 0; k < 5; k++) {
            float a = 0.f;
            for (int w = 0; w < LBLK / 32; w++) a += s5[w][k];
            g_part[blockIdx.x * 5 + k] = a;
        }
    }
}

// ---------------- final combine ----------------
__global__ void loss_final(const float* __restrict__ lv, float* __restrict__ out,
                           int out_size) {
    __shared__ double sd[BATCH][4];
    int t = threadIdx.x;
    if (t < BATCH) {
        double F = 0, Bd = 0, P = 0, T = 0, PT = 0;
        for (int b = 0; b < BPI; b++) {
            const float* pp = g_part + (t * BPI + b) * 5;
            F += pp[0]; Bd += pp[1]; P += pp[2]; T += pp[3]; PT += pp[4];
        }
        double total = P + T;
        double uni = total - PT;
        sd[t][0] = F;
        sd[t][1] = Bd;
        sd[t][2] = (2.0 * PT + 1e-6) / (total + 1e-6);
        sd[t][3] = (PT + 1e-6) / (uni + 1e-6);
    }
    __syncthreads();
    if (t == 0) {
        double F = 0, Bd = 0, D = 0, I = 0;
        for (int b = 0; b < BATCH; b++) {
            F += sd[b][0]; Bd += sd[b][1]; D += sd[b][2]; I += sd[b][3];
        }
        double N = (double)BATCH * (double)NPIX;
        double focal = F / N;
        double bnd   = Bd / N;
        double dice  = 1.0 - D / (double)BATCH;
        double iou   = 1.0 - I / (double)BATCH;
        double l0 = (double)lv[0], l1 = (double)lv[1], l2 = (double)lv[2], l3 = (double)lv[3];
        double tot = exp(-l0) * focal + l0
                   + exp(-l1) * dice  + l1
                   + exp(-l2) * bnd   + l2
                   + exp(-l3) * iou   + l3;
        if (out_size > 0) out[0] = (float)tot;
        if (out_size > 1) out[1] = (float)focal;
        if (out_size > 2) out[2] = (float)dice;
        if (out_size > 3) out[3] = (float)bnd;
        if (out_size > 4) out[4] = (float)iou;
    }
}

extern "C" void kernel_launch(void* const* d_in, const int* in_sizes, int n_in,
                              void* d_out, int out_size) {
    const float* pred   = (const float*)d_in[0];
    const int*   target = (const int*)d_in[1];
    const float* lv     = (const float*)d_in[2];
    float* out = (float*)d_out;

    cudaFuncSetAttribute(dt_kernel, cudaFuncAttributeMaxDynamicSharedMemorySize, DT_SMEM);
    dt_kernel<<<BATCH, DT_T, DT_SMEM>>>(target);
    loss_partial<<<NLB, LBLK>>>(pred, target);
    loss_final<<<1, 32>>>(lv, out, out_size);
}

// round 6
// speedup vs baseline: 1.1825x; 1.1825x over previous
#include <cuda_runtime.h>
#include <cuda_bf16.h>
#include <math.h>

#define H 512
#define W 512
#define BATCH 16
#define NPIX (H*W)
#define CA 0.955f
#define CB 1.3693f
#define CINF 1e6f
#define BIG 1e30f

#define LBLK 256
#define BPI 16
#define NLB (BATCH*BPI)

// ---------------- device scratch ----------------
__device__ float    g_dist[BATCH*NPIX];
__device__ float    g_mx[BATCH];
__device__ int      g_flags[BATCH];
__device__ float    g_part[NLB*5];
__device__ unsigned g_seed[BATCH*H*16];   // 512 KB seed bitmaps

// =============== seed kernel: bitmap + dilate/erode -> seed bits ===============
__global__ __launch_bounds__(128) void seed_kernel(const int* __restrict__ target) {
    __shared__ unsigned mbits[H * 18];     // guard-padded mask bitmap (36 KB)
    __shared__ int sflag[2];

    const int img = blockIdx.x;
    const int* tg = target + img * NPIX;
    unsigned* sb = g_seed + img * H * 16;

    const int tid  = threadIdx.x;
    const int lane = tid & 31;
    const int sl   = tid & 7;
    const int sg   = tid >> 3;
    const int col0 = tid * 4;
    const unsigned FM = 0xffffffffu;

    if (tid < 2) sflag[tid] = 0;
    for (int r = tid; r < H; r += 128) {
        mbits[r * 18 + 0]  = 0u;
        mbits[r * 18 + 17] = 0u;
    }
    __syncthreads();

    bool any1 = false, any0 = false;
    for (int r = 0; r < H; r++) {
        int4 tv = *(const int4*)(tg + r * W + col0);
        unsigned nib = (unsigned)(tv.x != 0) | ((unsigned)(tv.y != 0) << 1)
                     | ((unsigned)(tv.z != 0) << 2) | ((unsigned)(tv.w != 0) << 3);
        any1 |= (nib != 0u);
        any0 |= (nib != 15u);
        unsigned word = nib << (4 * sl);
        word |= __shfl_xor_sync(FM, word, 1);
        word |= __shfl_xor_sync(FM, word, 2);
        word |= __shfl_xor_sync(FM, word, 4);
        if (sl == 0) mbits[r * 18 + 1 + sg] = word;
    }
    if (__any_sync(FM, any1) && lane == 0) atomicOr(&sflag[0], 1);
    if (__any_sync(FM, any0) && lane == 0) atomicOr(&sflag[1], 1);
    __syncthreads();
    const int hasb = sflag[0] & sflag[1];

    for (int idx = tid; idx < H * 16; idx += 128) {
        int r = idx >> 4, w = idx & 15;
        unsigned swd;
        if (hasb) {
            unsigned dil = 0u, ero = 0xffffffffu;
            #pragma unroll
            for (int dr = -1; dr <= 1; dr++) {
                int r2 = r + dr;
                if (r2 < 0 || r2 >= H) continue;
                unsigned M  = mbits[r2 * 18 + 1 + w];
                unsigned Ml = mbits[r2 * 18 + w];
                unsigned Mr = mbits[r2 * 18 + 2 + w];
                unsigned Mlg = (w == 0)  ? 0xffffffffu : Ml;
                unsigned Mrg = (w == 15) ? 0xffffffffu : Mr;
                dil |= M | __funnelshift_l(Ml, M, 1) | __funnelshift_r(M, Mr, 1);
                ero &= M & __funnelshift_l(Mlg, M, 1) & __funnelshift_r(M, Mrg, 1);
            }
            swd = dil & ~ero;
        } else {
            swd = ~mbits[r * 18 + 1 + w];
        }
        sb[idx] = swd;
    }
    if (tid == 0) g_flags[img] = sflag[0] | (sflag[1] << 1);
}

// =============== dt kernel: ONE WARP per image, no barriers ===============
__global__ __launch_bounds__(32) void dt_warp_kernel() {
    const int img = blockIdx.x;
    const unsigned* sb = g_seed + img * H * 16;
    float* dd = g_dist + img * NPIX;

    const int t  = threadIdx.x;
    const int c0 = t * 16;
    const unsigned FM = 0xffffffffu;
    const int wsel = t >> 1;
    const int wsh  = (t & 1) * 16;

    float aj[16];
    #pragma unroll
    for (int c = 0; c < 16; c++) aj[c] = CA * (float)(c0 + c);
    const float ajL = CA * (float)(c0 - 1);
    const float ajR = CA * (float)(c0 + 16);

    // ================= forward pass =================
    float p[16];
    #pragma unroll
    for (int c = 0; c < 16; c++) p[c] = CINF;
    float pvL = CINF, pvR = CINF;

    unsigned hw = (sb[wsel] >> wsh) & 0xffffu;

    for (int i = 0; i < H; i++) {
        unsigned hwn = 0u;
        if (i < H - 1) hwn = (sb[(i + 1) * 16 + wsel] >> wsh) & 0xffffu;

        float v[16];
        #pragma unroll
        for (int c = 0; c < 16; c++) {
            float pl = (c == 0)  ? pvL : p[c - 1];
            float pr = (c == 15) ? pvR : p[c + 1];
            float d  = ((hw >> c) & 1u) ? 0.0f : CINF;
            float m = fminf(fminf(d, p[c] + CA), fminf(pl + CB, pr + CB));
            v[c] = m - aj[c];
        }
        float vR0 = __shfl_down_sync(FM, v[0], 1);

        // in-register Hillis-Steele prefix-min (descending order keeps prev-step reads)
        #pragma unroll
        for (int off = 1; off < 16; off <<= 1)
            #pragma unroll
            for (int c = 15; c >= off; c--)
                v[c] = fminf(v[c], v[c - off]);

        // warp inclusive scan of aggregates
        float s = v[15], o;
        o = __shfl_up_sync(FM, s, 1);  if (t >= 1)  s = fminf(s, o);
        o = __shfl_up_sync(FM, s, 2);  if (t >= 2)  s = fminf(s, o);
        o = __shfl_up_sync(FM, s, 4);  if (t >= 4)  s = fminf(s, o);
        o = __shfl_up_sync(FM, s, 8);  if (t >= 8)  s = fminf(s, o);
        o = __shfl_up_sync(FM, s, 16); if (t >= 16) s = fminf(s, o);
        float sLr = __shfl_up_sync(FM, s, 1);
        float excl = (t == 0) ? BIG : sLr;

        #pragma unroll
        for (int c = 0; c < 16; c++) p[c] = aj[c] + fminf(excl, v[c]);

        float* row = dd + i * W + c0;
        *(float4*)(row + 0)  = make_float4(p[0],  p[1],  p[2],  p[3]);
        *(float4*)(row + 4)  = make_float4(p[4],  p[5],  p[6],  p[7]);
        *(float4*)(row + 8)  = make_float4(p[8],  p[9],  p[10], p[11]);
        *(float4*)(row + 12) = make_float4(p[12], p[13], p[14], p[15]);

        pvL = (t == 0)  ? CINF : (ajL + excl);               // left nbr out[15], exact
        pvR = (t == 31) ? CINF : (ajR + fminf(s, vR0));      // right nbr out[0], exact
        hw = hwn;
    }

    // ================= backward pass =================
    float ar[16];
    #pragma unroll
    for (int c = 0; c < 16; c++) ar[c] = CA * (float)(W - 1 - (c0 + c));
    const float arL = CA * (float)(W - c0);       // W-1-(c0-1)
    const float arR = CA * (float)(W - 17 - c0);  // W-1-(c0+16)

    #pragma unroll
    for (int c = 0; c < 16; c++) p[c] = CINF;
    pvL = CINF; pvR = CINF;
    float lmax = 0.0f;

    float4 cu0, cu1, cu2, cu3;
    {
        const float* row = dd + (H - 1) * W + c0;
        cu0 = *(const float4*)(row + 0);
        cu1 = *(const float4*)(row + 4);
        cu2 = *(const float4*)(row + 8);
        cu3 = *(const float4*)(row + 12);
    }

    for (int i = H - 1; i >= 0; i--) {
        float drw[16] = {cu0.x,cu0.y,cu0.z,cu0.w, cu1.x,cu1.y,cu1.z,cu1.w,
                         cu2.x,cu2.y,cu2.z,cu2.w, cu3.x,cu3.y,cu3.z,cu3.w};
        if (i > 0) {
            const float* row = dd + (i - 1) * W + c0;
            cu0 = *(const float4*)(row + 0);
            cu1 = *(const float4*)(row + 4);
            cu2 = *(const float4*)(row + 8);
            cu3 = *(const float4*)(row + 12);
        }

        float v[16];
        #pragma unroll
        for (int c = 0; c < 16; c++) {
            float pl = (c == 0)  ? pvL : p[c - 1];
            float pr = (c == 15) ? pvR : p[c + 1];
            float m = fminf(fminf(drw[c], p[c] + CA), fminf(pl + CB, pr + CB));
            v[c] = m - ar[c];
        }
        float vL15 = __shfl_up_sync(FM, v[15], 1);

        // in-register suffix-min (ascending order keeps prev-step reads)
        #pragma unroll
        for (int off = 1; off < 16; off <<= 1)
            #pragma unroll
            for (int c = 0; c <= 15 - off; c++)
                v[c] = fminf(v[c], v[c + off]);

        // warp inclusive suffix scan
        float s = v[0], o;
        o = __shfl_down_sync(FM, s, 1);  if (t <= 30) s = fminf(s, o);
        o = __shfl_down_sync(FM, s, 2);  if (t <= 29) s = fminf(s, o);
        o = __shfl_down_sync(FM, s, 4);  if (t <= 27) s = fminf(s, o);
        o = __shfl_down_sync(FM, s, 8);  if (t <= 23) s = fminf(s, o);
        o = __shfl_down_sync(FM, s, 16); if (t <= 15) s = fminf(s, o);
        float sRr = __shfl_down_sync(FM, s, 1);
        float excl = (t == 31) ? BIG : sRr;

        #pragma unroll
        for (int c = 0; c < 16; c++) {
            p[c] = ar[c] + fminf(excl, v[c]);
            lmax = fmaxf(lmax, p[c]);
        }

        float* row = dd + i * W + c0;
        *(float4*)(row + 0)  = make_float4(p[0],  p[1],  p[2],  p[3]);
        *(float4*)(row + 4)  = make_float4(p[4],  p[5],  p[6],  p[7]);
        *(float4*)(row + 8)  = make_float4(p[8],  p[9],  p[10], p[11]);
        *(float4*)(row + 12) = make_float4(p[12], p[13], p[14], p[15]);

        pvR = (t == 31) ? CINF : (arR + excl);               // right nbr out[0], exact
        pvL = (t == 0)  ? CINF : (arL + fminf(s, vL15));     // left nbr out[15], exact
    }

    // per-image max
    #pragma unroll
    for (int d = 16; d > 0; d >>= 1)
        lmax = fmaxf(lmax, __shfl_xor_sync(FM, lmax, d));
    if (t == 0) g_mx[img] = lmax;
}

// ---------------- loss partial sums ----------------
__global__ __launch_bounds__(LBLK) void loss_partial(const float* __restrict__ pred,
                                                     const int* __restrict__ target) {
    const int img = blockIdx.x / BPI;
    const int sub = blockIdx.x % BPI;
    const int base = img * NPIX;
    const float mx = g_mx[img];
    const int hfg = g_flags[img] & 1;
    const float inv = 1.0f / fmaxf(mx, 1e-12f);
    const int usediv = (mx > 0.0f) ? 1 : 0;

    float sF = 0.f, sB = 0.f, sP = 0.f, sT = 0.f, sPT = 0.f;
    for (int idx = sub * LBLK + threadIdx.x; idx < NPIX; idx += BPI * LBLK) {
        float x = pred[base + idx];
        int tv = target[base + idx];
        float d = g_dist[base + idx];
        float p = 1.0f / (1.0f + expf(-x));
        float ax = fabsf(x);
        float bce = log1pf(expf(-ax)) + (tv ? fmaxf(-x, 0.0f) : fmaxf(x, 0.0f));
        float pt = tv ? p : (1.0f - p);
        float omp = 1.0f - pt;
        float alpha = tv ? 0.25f : 0.75f;
        sF += alpha * omp * omp * bce;
        float dn = hfg ? (usediv ? d * inv : d) : 1.0f;
        sB += omp * (1.0f + dn);
        sP += p;
        if (tv) { sT += 1.0f; sPT += p; }
    }

    float vals[5] = {sF, sB, sP, sT, sPT};
    #pragma unroll
    for (int k = 0; k < 5; k++) {
        float v = vals[k];
        #pragma unroll
        for (int d = 16; d > 0; d >>= 1) v += __shfl_xor_sync(0xffffffffu, v, d);
        vals[k] = v;
    }
    __shared__ float s5[LBLK / 32][5];
    int lane = threadIdx.x & 31, wid = threadIdx.x >> 5;
    if (lane == 0) {
        #pragma unroll
        for (int k = 0; k < 5; k++) s5[wid][k] = vals[k];
    }
    __syncthreads();
    if (threadIdx.x == 0) {
        #pragma unroll
        for (int k = 0; k < 5; k++) {
            float a = 0.f;
            for (int w = 0; w < LBLK / 32; w++) a += s5[w][k];
            g_part[blockIdx.x * 5 + k] = a;
        }
    }
}

// ---------------- final combine ----------------
__global__ void loss_final(const float* __restrict__ lv, float* __restrict__ out,
                           int out_size) {
    __shared__ double sd[BATCH][4];
    int t = threadIdx.x;
    if (t < BATCH) {
        double F = 0, Bd = 0, P = 0, T = 0, PT = 0;
        for (int b = 0; b < BPI; b++) {
            const float* pp = g_part + (t * BPI + b) * 5;
            F += pp[0]; Bd += pp[1]; P += pp[2]; T += pp[3]; PT += pp[4];
        }
        double total = P + T;
        double uni = total - PT;
        sd[t][0] = F;
        sd[t][1] = Bd;
        sd[t][2] = (2.0 * PT + 1e-6) / (total + 1e-6);
        sd[t][3] = (PT + 1e-6) / (uni + 1e-6);
    }
    __syncthreads();
    if (t == 0) {
        double F = 0, Bd = 0, D = 0, I = 0;
        for (int b = 0; b < BATCH; b++) {
            F += sd[b][0]; Bd += sd[b][1]; D += sd[b][2]; I += sd[b][3];
        }
        double N = (double)BATCH * (double)NPIX;
        double focal = F / N;
        double bnd   = Bd / N;
        double dice  = 1.0 - D / (double)BATCH;
        double iou   = 1.0 - I / (double)BATCH;
        double l0 = (double)lv[0], l1 = (double)lv[1], l2 = (double)lv[2], l3 = (double)lv[3];
        double tot = exp(-l0) * focal + l0
                   + exp(-l1) * dice  + l1
                   + exp(-l2) * bnd   + l2
                   + exp(-l3) * iou   + l3;
        if (out_size > 0) out[0] = (float)tot;
        if (out_size > 1) out[1] = (float)focal;
        if (out_size > 2) out[2] = (float)dice;
        if (out_size > 3) out[3] = (float)bnd;
        if (out_size > 4) out[4] = (float)iou;
    }
}

extern "C" void kernel_launch(void* const* d_in, const int* in_sizes, int n_in,
                              void* d_out, int out_size) {
    const float* pred   = (const float*)d_in[0];
    const int*   target = (const int*)d_in[1];
    const float* lv     = (const float*)d_in[2];
    float* out = (float*)d_out;

    seed_kernel<<<BATCH, 128>>>(target);
    dt_warp_kernel<<<BATCH, 32>>>();
    loss_partial<<<NLB, LBLK>>>(pred, target);
    loss_final<<<1, 32>>>(lv, out, out_size);
}